// round 6
// baseline (speedup 1.0000x reference)
#include <cuda_runtime.h>
#include <math.h>

// Problem constants
#define Bn 16
#define Tn 2048
#define Dn 1024
#define Cn 512
#define MT 64                     // rows per block
#define KT 16                     // K depth per smem step
#define NBLK ((Bn * Tn) / MT)     // 512 blocks
#define NSTEP (Dn / KT)           // 64 K-steps
#define WS_STRIDE 516             // padded row stride for W smem (bank decorrelation)
#define AS_FLOATS (2 * KT * MT)          // 2048
#define WS_FLOATS (2 * KT * WS_STRIDE)   // 16512
#define SMEM_FLOATS (AS_FLOATS + WS_FLOATS)
#define SMEM_BYTES (SMEM_FLOATS * 4)     // 74240 B

// Scratch (no allocations allowed -> __device__ globals)
__device__ float g_colsum[NBLK * Cn];    // per-block column sums of cam (1 MB)
__device__ float g_lterm[Bn];            // per-batch CE terms

typedef unsigned long long u64t;

__device__ __forceinline__ u64t dup2(float x) {
    u64t r; unsigned xi = __float_as_uint(x);
    asm("mov.b64 %0, {%1, %1};" : "=l"(r) : "r"(xi));
    return r;
}
__device__ __forceinline__ u64t fma2(u64t a, u64t b, u64t c) {
    u64t d;
    asm("fma.rn.f32x2 %0, %1, %2, %3;" : "=l"(d) : "l"(a), "l"(b), "l"(c));
    return d;
}
__device__ __forceinline__ void unpack2(u64t p, float& lo, float& hi) {
    unsigned a, b;
    asm("mov.b64 {%0, %1}, %2;" : "=r"(a), "=r"(b) : "l"(p));
    lo = __uint_as_float(a); hi = __uint_as_float(b);
}

// ---------------------------------------------------------------------------
// Kernel 1: fused CAM GEMM + row softmax (written twice) + column-sum scratch
// Grid: 512 blocks x 512 threads. Each block: rows [blk*64, blk*64+64), all 512 cols.
// Thread (ty = tid>>5 in [0,16), tx = tid&31): rows ty*4..ty*4+3,
// col pairs {2*tx, 2*tx+1} + 64*j for j in [0,8).
// ---------------------------------------------------------------------------
__global__ void __launch_bounds__(512)
cam_kernel(const float* __restrict__ feat, const float* __restrict__ W,
           float* __restrict__ out_soft, float* __restrict__ out_raw)
{
    extern __shared__ float smem[];
    float* As = smem;               // [2][KT][MT]  k-major
    float* Ws = smem + AS_FLOATS;   // [2][KT][WS_STRIDE] k-major

    const int tid = threadIdx.x;
    const int tx  = tid & 31;
    const int ty  = tid >> 5;       // warp id == ty
    const int blk = blockIdx.x;
    const int r0  = blk * MT;

    u64t acc[4][8];
#pragma unroll
    for (int i = 0; i < 4; i++)
#pragma unroll
        for (int j = 0; j < 8; j++) acc[i][j] = 0ull;

    // register staging for global->smem (transposed store)
    float4 sa;
    float4 sw[4];
    const int arow = tid >> 2;   // valid for tid<256: 0..63
    const int acg  = tid & 3;

    auto LOADR = [&](int k0) {
        if (tid < 256)
            sa = *(const float4*)&feat[(size_t)(r0 + arow) * Dn + k0 + acg * 4];
#pragma unroll
        for (int w = 0; w < 4; w++) {
            int lin = w * 512 + tid;
            int c = lin >> 2, cg = lin & 3;
            sw[w] = *(const float4*)&W[(size_t)c * Dn + k0 + cg * 4];
        }
    };
    auto STORER = [&](int buf) {
        if (tid < 256) {
            float* a = &As[buf * KT * MT + (acg * 4) * MT + arow];
            a[0] = sa.x; a[MT] = sa.y; a[2 * MT] = sa.z; a[3 * MT] = sa.w;
        }
#pragma unroll
        for (int w = 0; w < 4; w++) {
            int lin = w * 512 + tid;
            int c = lin >> 2, cg = lin & 3;
            float* p = &Ws[buf * KT * WS_STRIDE + (cg * 4) * WS_STRIDE + c];
            p[0] = sw[w].x; p[WS_STRIDE] = sw[w].y;
            p[2 * WS_STRIDE] = sw[w].z; p[3 * WS_STRIDE] = sw[w].w;
        }
    };
    auto COMPUTE = [&](int buf) {
        const float* Ab = &As[buf * KT * MT];
        const float* Wb = &Ws[buf * KT * WS_STRIDE];
#pragma unroll
        for (int kk = 0; kk < KT; kk++) {
            float4 av = *(const float4*)&Ab[kk * MT + ty * 4];
            u64t a0 = dup2(av.x), a1 = dup2(av.y), a2 = dup2(av.z), a3 = dup2(av.w);
            const float* wr = &Wb[kk * WS_STRIDE + 2 * tx];
#pragma unroll
            for (int j = 0; j < 8; j++) {
                u64t bv = *(const u64t*)&wr[64 * j];
                acc[0][j] = fma2(a0, bv, acc[0][j]);
                acc[1][j] = fma2(a1, bv, acc[1][j]);
                acc[2][j] = fma2(a2, bv, acc[2][j]);
                acc[3][j] = fma2(a3, bv, acc[3][j]);
            }
        }
    };

    // prologue
    LOADR(0);
    STORER(0);
    __syncthreads();

#pragma unroll 1
    for (int s = 0; s < NSTEP; s++) {
        if (s + 1 < NSTEP) LOADR((s + 1) * KT);   // LDGs issue early, overlap compute
        COMPUTE(s & 1);
        if (s + 1 < NSTEP) STORER((s + 1) & 1);
        __syncthreads();
    }

    // ---- column sums (for logits) into smem, then deterministic scratch ----
    float* cs = smem;            // reuse As region (512 <= 2048 floats)
    cs[tid] = 0.f;               // tid in [0,512) == Cn
    __syncthreads();
#pragma unroll
    for (int j = 0; j < 8; j++) {
        float s0 = 0.f, s1 = 0.f;
#pragma unroll
        for (int i = 0; i < 4; i++) {
            float lo, hi; unpack2(acc[i][j], lo, hi);
            s0 += lo; s1 += hi;
        }
        int c0 = 2 * tx + 64 * j;
        atomicAdd(&cs[c0], s0);
        atomicAdd(&cs[c0 + 1], s1);
    }
    __syncthreads();
    __stcs(&g_colsum[(size_t)blk * Cn + tid], cs[tid]);

    // ---- row softmax, written to both outputs (streaming stores) ----
#pragma unroll
    for (int i = 0; i < 4; i++) {
        float v[16];
#pragma unroll
        for (int j = 0; j < 8; j++) unpack2(acc[i][j], v[2 * j], v[2 * j + 1]);
        float m = v[0];
#pragma unroll
        for (int k = 1; k < 16; k++) m = fmaxf(m, v[k]);
#pragma unroll
        for (int off = 16; off > 0; off >>= 1)
            m = fmaxf(m, __shfl_xor_sync(0xffffffffu, m, off));
        float ssum = 0.f;
#pragma unroll
        for (int k = 0; k < 16; k++) { v[k] = __expf(v[k] - m); ssum += v[k]; }
#pragma unroll
        for (int off = 16; off > 0; off >>= 1)
            ssum += __shfl_xor_sync(0xffffffffu, ssum, off);
        float inv = 1.0f / ssum;
        size_t base = (size_t)(r0 + ty * 4 + i) * Cn;
#pragma unroll
        for (int j = 0; j < 8; j++) {
            float2 o; o.x = v[2 * j] * inv; o.y = v[2 * j + 1] * inv;
            __stcs((float2*)&out_soft[base + 2 * tx + 64 * j], o);
            __stcs((float2*)&out_raw [base + 2 * tx + 64 * j], o);
        }
    }
}

// ---------------------------------------------------------------------------
// Kernel 2: logits = mean_t(cam) + bias ; per-batch log-softmax CE term
// Grid: Bn blocks x Cn threads. labels read as int32 (JAX default x64-disabled).
// ---------------------------------------------------------------------------
__global__ void __launch_bounds__(Cn)
logits_kernel(const float* __restrict__ bias, const int* __restrict__ labels,
              float* __restrict__ out_logits)
{
    __shared__ float sm_log[Cn];
    __shared__ float redm[16], reds[16];
    __shared__ float sMax;

    const int b = blockIdx.x;
    const int c = threadIdx.x;
    const int lane = c & 31, wid = c >> 5;

    float s = 0.f;
    const int base = b * (Tn / MT);   // 32 tiles per batch
#pragma unroll 4
    for (int mb = 0; mb < Tn / MT; mb++) s += g_colsum[(size_t)(base + mb) * Cn + c];
    float logit = s * (1.0f / Tn) + bias[c];
    out_logits[b * Cn + c] = logit;
    sm_log[c] = logit;

    float m = logit;
#pragma unroll
    for (int off = 16; off > 0; off >>= 1)
        m = fmaxf(m, __shfl_xor_sync(0xffffffffu, m, off));
    if (lane == 0) redm[wid] = m;
    __syncthreads();
    if (c == 0) {
        float mm = redm[0];
        for (int i = 1; i < 16; i++) mm = fmaxf(mm, redm[i]);
        sMax = mm;
    }
    __syncthreads();

    float e = expf(logit - sMax);
#pragma unroll
    for (int off = 16; off > 0; off >>= 1)
        e += __shfl_xor_sync(0xffffffffu, e, off);
    if (lane == 0) reds[wid] = e;
    __syncthreads();
    if (c == 0) {
        float ss = 0.f;
        for (int i = 0; i < 16; i++) ss += reds[i];
        int lab = labels[b];
        g_lterm[b] = -(sm_log[lab] - sMax - logf(ss));
    }
}

// Kernel 3: final loss scalar
__global__ void loss_kernel(float* __restrict__ out_loss)
{
    if (threadIdx.x == 0) {
        float s = 0.f;
        for (int b = 0; b < Bn; b++) s += g_lterm[b];
        out_loss[0] = s * (1.0f / Bn);
    }
}

extern "C" void kernel_launch(void* const* d_in, const int* in_sizes, int n_in,
                              void* d_out, int out_size)
{
    const float* feat   = (const float*)d_in[0];
    const int*   labels = (const int*)d_in[1];     // int32 (JAX x64 disabled)
    const float* W      = (const float*)d_in[2];
    const float* bias   = (const float*)d_in[3];

    float* out        = (float*)d_out;
    float* out_soft   = out;
    float* out_raw    = out + (size_t)Bn * Tn * Cn;
    float* out_logits = out + 2 * (size_t)Bn * Tn * Cn;
    float* out_loss   = out_logits + Bn * Cn;

    cudaFuncSetAttribute(cam_kernel, cudaFuncAttributeMaxDynamicSharedMemorySize, SMEM_BYTES);

    cam_kernel<<<NBLK, 512, SMEM_BYTES>>>(feat, W, out_soft, out_raw);
    logits_kernel<<<Bn, Cn>>>(bias, labels, out_logits);
    loss_kernel<<<1, 32>>>(out_loss);
}

// round 9
// speedup vs baseline: 2.2290x; 2.2290x over previous
#include <cuda_runtime.h>
#include <cuda_bf16.h>
#include <math.h>
#include <stdint.h>

// ---------------- problem constants ----------------
#define Bn 16
#define Tn 2048
#define Dn 1024
#define Cn 512
#define MTILE 64                   // rows per CTA
#define KC 32                      // K per chunk
#define NCH (Dn / KC)              // 32 chunks
#define NBLK ((Bn * Tn) / MTILE)   // 512 CTAs
#define RSB 80                     // smem row stride in BYTES (40 bf16) — ldmatrix conflict-free

// ---------------- smem layout (bytes) ----------------
#define SM_AH 0
#define SM_AL (MTILE * RSB)            // 5120
#define SM_BH (2 * MTILE * RSB)        // 10240
#define SM_BL (SM_BH + Cn * RSB)       // 51200
#define STAGE (SM_BL + Cn * RSB)       // 92160
#define SM_TOTAL (2 * STAGE)           // 184320

// epilogue aliases (float indices)
#define EP_CS  0      // colsum[512]
#define EP_M   512    // sm_m[64][8]
#define EP_S   1024   // sm_s[64][8]
#define EP_MM  1536   // sm_M[64]
#define EP_INV 1600   // sm_inv[64]

// ---------------- device scratch ----------------
__device__ __align__(256) __nv_bfloat16 g_Whi[Cn * Dn];
__device__ __align__(256) __nv_bfloat16 g_Wlo[Cn * Dn];
__device__ float g_colsum[NBLK * Cn];
__device__ float g_lterm[Bn];

// ---------------- ptx helpers ----------------
__device__ __forceinline__ uint32_t s2u(const void* p) {
    uint32_t a;
    asm("{ .reg .u64 t; cvta.to.shared.u64 t, %1; cvt.u32.u64 %0, t; }" : "=r"(a) : "l"(p));
    return a;
}
__device__ __forceinline__ void cpa16(uint32_t dst, const void* src) {
    asm volatile("cp.async.cg.shared.global [%0], [%1], 16;" :: "r"(dst), "l"(src));
}
__device__ __forceinline__ void ldsm4(uint32_t addr, uint32_t* r) {
    asm volatile("ldmatrix.sync.aligned.m8n8.x4.shared.b16 {%0,%1,%2,%3}, [%4];"
                 : "=r"(r[0]), "=r"(r[1]), "=r"(r[2]), "=r"(r[3]) : "r"(addr));
}
__device__ __forceinline__ void mma16816(float* c, const uint32_t* a, const uint32_t* b) {
    asm volatile("mma.sync.aligned.m16n8k16.row.col.f32.bf16.bf16.f32 "
                 "{%0,%1,%2,%3}, {%4,%5,%6,%7}, {%8,%9}, {%0,%1,%2,%3};"
                 : "+f"(c[0]), "+f"(c[1]), "+f"(c[2]), "+f"(c[3])
                 : "r"(a[0]), "r"(a[1]), "r"(a[2]), "r"(a[3]), "r"(b[0]), "r"(b[1]));
}

// ---------------------------------------------------------------------------
// Kernel 0: split W (fp32) into bf16 hi/lo
// ---------------------------------------------------------------------------
__global__ void __launch_bounds__(512)
wsplit_kernel(const float* __restrict__ W)
{
    int i = blockIdx.x * 512 + threadIdx.x;
    float x = W[i];
    __nv_bfloat16 h = __float2bfloat16(x);
    g_Whi[i] = h;
    g_Wlo[i] = __float2bfloat16(x - __bfloat162float(h));
}

// ---------------------------------------------------------------------------
// Kernel 1: bf16 3-split mma.sync GEMM + softmax epilogue + colsum
// CTA: 64 rows x 512 cols. 16 warps, warp tile 32x64 (2 M-tiles x 8 N-tiles).
// ---------------------------------------------------------------------------
__global__ void __launch_bounds__(512, 1)
cam_mma_kernel(const float* __restrict__ feat,
               float* __restrict__ out_soft, float* __restrict__ out_raw)
{
    extern __shared__ char smem[];
    float* smf = (float*)smem;
    const uint32_t sb = s2u(smem);
    const int tid  = threadIdx.x;
    const int w    = tid >> 5, lane = tid & 31;
    const int Rbase = blockIdx.x * MTILE;
    const int mrow0 = (w & 1) * 32;
    const int n0    = (w >> 1) * 64;

    float acc[2][8][4];
#pragma unroll
    for (int mt = 0; mt < 2; mt++)
#pragma unroll
        for (int nt = 0; nt < 8; nt++)
#pragma unroll
            for (int k = 0; k < 4; k++) acc[mt][nt][k] = 0.f;

    // ---- load helpers ----
    const int ar = tid >> 3, aq = tid & 7;     // A: row 0..63, float4-group 0..7
    auto LDGA = [&](int k0) -> float4 {
        return *(const float4*)&feat[(size_t)(Rbase + ar) * Dn + k0 + aq * 4];
    };
    auto STSA = [&](int buf, float4 v) {
        __nv_bfloat16 h0 = __float2bfloat16(v.x), h1 = __float2bfloat16(v.y);
        __nv_bfloat16 h2 = __float2bfloat16(v.z), h3 = __float2bfloat16(v.w);
        __nv_bfloat16 l0 = __float2bfloat16(v.x - __bfloat162float(h0));
        __nv_bfloat16 l1 = __float2bfloat16(v.y - __bfloat162float(h1));
        __nv_bfloat16 l2 = __float2bfloat16(v.z - __bfloat162float(h2));
        __nv_bfloat16 l3 = __float2bfloat16(v.w - __bfloat162float(h3));
        uint2 hv, lv;
        hv.x = (uint32_t)__bfloat16_as_ushort(h0) | ((uint32_t)__bfloat16_as_ushort(h1) << 16);
        hv.y = (uint32_t)__bfloat16_as_ushort(h2) | ((uint32_t)__bfloat16_as_ushort(h3) << 16);
        lv.x = (uint32_t)__bfloat16_as_ushort(l0) | ((uint32_t)__bfloat16_as_ushort(l1) << 16);
        lv.y = (uint32_t)__bfloat16_as_ushort(l2) | ((uint32_t)__bfloat16_as_ushort(l3) << 16);
        char* base = smem + buf * STAGE + ar * RSB + aq * 8;
        *(uint2*)(base + SM_AH) = hv;
        *(uint2*)(base + SM_AL) = lv;
    };
    auto LDB = [&](int buf, int k0) {
#pragma unroll
        for (int i = 0; i < 4; i++) {
            int g = tid + i * 512;             // 0..2047
            int row = g >> 2, grp = g & 3;
            uint32_t dst = sb + buf * STAGE + row * RSB + grp * 16;
            const __nv_bfloat16* sh = g_Whi + (size_t)row * Dn + k0 + grp * 8;
            const __nv_bfloat16* sl = g_Wlo + (size_t)row * Dn + k0 + grp * 8;
            cpa16(dst + SM_BH, sh);
            cpa16(dst + SM_BL, sl);
        }
        asm volatile("cp.async.commit_group;" ::: "memory");
    };

    // ldmatrix lane addressing
    const int alr = lane & 15;                       // A row-within-16
    const int akb = ((lane >> 4) & 1) * 16;          // A k-half byte
    const int brow = ((lane >> 4) & 1) * 8 + (lane & 7); // B row-within-16
    const int bkb = ((lane >> 3) & 1) * 16;          // B k-half byte

    auto COMPUTE = [&](int buf) {
        const uint32_t st = sb + buf * STAGE;
#pragma unroll
        for (int ks = 0; ks < 2; ks++) {
            uint32_t ah[2][4], al[2][4];
#pragma unroll
            for (int mt = 0; mt < 2; mt++) {
                uint32_t arow = (mrow0 + mt * 16 + alr) * RSB + ks * 32 + akb;
                ldsm4(st + SM_AH + arow, ah[mt]);
                ldsm4(st + SM_AL + arow, al[mt]);
            }
#pragma unroll
            for (int bt = 0; bt < 4; bt++) {
                uint32_t bh[4], bl[4];
                uint32_t boff = (n0 + bt * 16 + brow) * RSB + ks * 32 + bkb;
                ldsm4(st + SM_BH + boff, bh);
                ldsm4(st + SM_BL + boff, bl);
#pragma unroll
                for (int mt = 0; mt < 2; mt++)
#pragma unroll
                    for (int n2 = 0; n2 < 2; n2++) {
                        float* C = acc[mt][bt * 2 + n2];
                        mma16816(C, ah[mt], bh + n2 * 2);
                        mma16816(C, ah[mt], bl + n2 * 2);
                        mma16816(C, al[mt], bh + n2 * 2);
                    }
            }
        }
    };

    // ---- prologue ----
    float4 areg = LDGA(0);
    LDB(0, 0);
    STSA(0, areg);
    asm volatile("cp.async.wait_group 0;" ::: "memory");
    __syncthreads();

    // ---- mainloop ----
#pragma unroll 1
    for (int c = 0; c < NCH; c++) {
        if (c + 1 < NCH) {
            areg = LDGA((c + 1) * KC);
            LDB((c + 1) & 1, (c + 1) * KC);
        }
        COMPUTE(c & 1);
        if (c + 1 < NCH) {
            STSA((c + 1) & 1, areg);
            asm volatile("cp.async.wait_group 0;" ::: "memory");
        }
        __syncthreads();
    }

    // ---------------- epilogue ----------------
    // thread rows: mrow0 + mt*16 + h*8 + (lane>>2);  cols: n0 + nt*8 + 2*(lane&3)+{0,1}
    smf[EP_CS + tid] = 0.f;

    // row max
    float rm[2][2];
#pragma unroll
    for (int mt = 0; mt < 2; mt++)
#pragma unroll
        for (int h = 0; h < 2; h++) {
            float m = -INFINITY;
#pragma unroll
            for (int nt = 0; nt < 8; nt++)
                m = fmaxf(m, fmaxf(acc[mt][nt][h * 2], acc[mt][nt][h * 2 + 1]));
            m = fmaxf(m, __shfl_xor_sync(0xffffffffu, m, 1));
            m = fmaxf(m, __shfl_xor_sync(0xffffffffu, m, 2));
            rm[mt][h] = m;
        }
    if ((lane & 3) == 0)
#pragma unroll
        for (int mt = 0; mt < 2; mt++)
#pragma unroll
            for (int h = 0; h < 2; h++) {
                int rl = mrow0 + mt * 16 + h * 8 + (lane >> 2);
                smf[EP_M + rl * 8 + (w >> 1)] = rm[mt][h];
            }
    __syncthreads();
    if (tid < 64) {
        float M = smf[EP_M + tid * 8];
#pragma unroll
        for (int i = 1; i < 8; i++) M = fmaxf(M, smf[EP_M + tid * 8 + i]);
        smf[EP_MM + tid] = M;
    }
    __syncthreads();

    // exp-sum
    float Mrow[2][2];
#pragma unroll
    for (int mt = 0; mt < 2; mt++)
#pragma unroll
        for (int h = 0; h < 2; h++) {
            int rl = mrow0 + mt * 16 + h * 8 + (lane >> 2);
            Mrow[mt][h] = smf[EP_MM + rl];
            float s = 0.f;
#pragma unroll
            for (int nt = 0; nt < 8; nt++) {
                s += __expf(acc[mt][nt][h * 2]     - Mrow[mt][h]);
                s += __expf(acc[mt][nt][h * 2 + 1] - Mrow[mt][h]);
            }
            s += __shfl_xor_sync(0xffffffffu, s, 1);
            s += __shfl_xor_sync(0xffffffffu, s, 2);
            if ((lane & 3) == 0) smf[EP_S + rl * 8 + (w >> 1)] = s;
        }
    __syncthreads();
    if (tid < 64) {
        float S = 0.f;
#pragma unroll
        for (int i = 0; i < 8; i++) S += smf[EP_S + tid * 8 + i];
        smf[EP_INV + tid] = 1.0f / S;
    }
    __syncthreads();

    // store softmax (both outputs) + colsum
    float inv[2][2];
#pragma unroll
    for (int mt = 0; mt < 2; mt++)
#pragma unroll
        for (int h = 0; h < 2; h++) {
            int rl = mrow0 + mt * 16 + h * 8 + (lane >> 2);
            inv[mt][h] = smf[EP_INV + rl];
        }
#pragma unroll
    for (int mt = 0; mt < 2; mt++)
#pragma unroll
        for (int h = 0; h < 2; h++) {
            int rl = mrow0 + mt * 16 + h * 8 + (lane >> 2);
            size_t gbase = (size_t)(Rbase + rl) * Cn + n0 + 2 * (lane & 3);
#pragma unroll
            for (int nt = 0; nt < 8; nt++) {
                float2 o;
                o.x = __expf(acc[mt][nt][h * 2]     - Mrow[mt][h]) * inv[mt][h];
                o.y = __expf(acc[mt][nt][h * 2 + 1] - Mrow[mt][h]) * inv[mt][h];
                __stcs((float2*)&out_soft[gbase + nt * 8], o);
                __stcs((float2*)&out_raw [gbase + nt * 8], o);
            }
        }
    // colsum over this warp's 32 rows
#pragma unroll
    for (int nt = 0; nt < 8; nt++)
#pragma unroll
        for (int cc = 0; cc < 2; cc++) {
            float s = 0.f;
#pragma unroll
            for (int mt = 0; mt < 2; mt++)
#pragma unroll
                for (int h = 0; h < 2; h++) s += acc[mt][nt][h * 2 + cc];
            s += __shfl_xor_sync(0xffffffffu, s, 4);
            s += __shfl_xor_sync(0xffffffffu, s, 8);
            s += __shfl_xor_sync(0xffffffffu, s, 16);
            if (lane < 4)
                atomicAdd(&smf[EP_CS + n0 + nt * 8 + 2 * (lane & 3) + cc], s);
        }
    __syncthreads();
    __stcs(&g_colsum[(size_t)blockIdx.x * Cn + tid], smf[EP_CS + tid]);
}

// ---------------------------------------------------------------------------
// Kernel 2: logits = mean_t(cam) + bias; per-batch log-softmax CE term
// ---------------------------------------------------------------------------
__global__ void __launch_bounds__(Cn)
logits_kernel(const float* __restrict__ bias, const int* __restrict__ labels,
              float* __restrict__ out_logits)
{
    __shared__ float sm_log[Cn];
    __shared__ float redm[16], reds[16];
    __shared__ float sMax;

    const int b = blockIdx.x;
    const int c = threadIdx.x;
    const int lane = c & 31, wid = c >> 5;

    float s = 0.f;
    const int base = b * (Tn / MTILE);   // 32 tiles per batch
#pragma unroll 4
    for (int mb = 0; mb < Tn / MTILE; mb++) s += g_colsum[(size_t)(base + mb) * Cn + c];
    float logit = s * (1.0f / Tn) + bias[c];
    out_logits[b * Cn + c] = logit;
    sm_log[c] = logit;

    float m = logit;
#pragma unroll
    for (int off = 16; off > 0; off >>= 1)
        m = fmaxf(m, __shfl_xor_sync(0xffffffffu, m, off));
    if (lane == 0) redm[wid] = m;
    __syncthreads();
    if (c == 0) {
        float mm = redm[0];
        for (int i = 1; i < 16; i++) mm = fmaxf(mm, redm[i]);
        sMax = mm;
    }
    __syncthreads();

    float e = expf(logit - sMax);
#pragma unroll
    for (int off = 16; off > 0; off >>= 1)
        e += __shfl_xor_sync(0xffffffffu, e, off);
    if (lane == 0) reds[wid] = e;
    __syncthreads();
    if (c == 0) {
        float ss = 0.f;
        for (int i = 0; i < 16; i++) ss += reds[i];
        int lab = labels[b];
        g_lterm[b] = -(sm_log[lab] - sMax - logf(ss));
    }
}

__global__ void loss_kernel(float* __restrict__ out_loss)
{
    if (threadIdx.x == 0) {
        float s = 0.f;
        for (int b = 0; b < Bn; b++) s += g_lterm[b];
        out_loss[0] = s * (1.0f / Bn);
    }
}

// ---------------------------------------------------------------------------
extern "C" void kernel_launch(void* const* d_in, const int* in_sizes, int n_in,
                              void* d_out, int out_size)
{
    const float* feat   = (const float*)d_in[0];
    const int*   labels = (const int*)d_in[1];     // int32 (JAX x64 disabled)
    const float* W      = (const float*)d_in[2];
    const float* bias   = (const float*)d_in[3];

    float* out        = (float*)d_out;
    float* out_soft   = out;
    float* out_raw    = out + (size_t)Bn * Tn * Cn;
    float* out_logits = out + 2 * (size_t)Bn * Tn * Cn;
    float* out_loss   = out_logits + Bn * Cn;

    cudaFuncSetAttribute(cam_mma_kernel, cudaFuncAttributeMaxDynamicSharedMemorySize, SM_TOTAL);

    wsplit_kernel<<<(Cn * Dn) / 512, 512>>>(W);
    cam_mma_kernel<<<NBLK, 512, SM_TOTAL>>>(feat, out_soft, out_raw);
    logits_kernel<<<Bn, Cn>>>(bias, labels, out_logits);
    loss_kernel<<<1, 32>>>(out_loss);
}